// round 8
// baseline (speedup 1.0000x reference)
#include <cuda_runtime.h>
#include <cuda_bf16.h>

#define TPB    256
#define NBLK   592             // 148 SMs * 4 CTAs
#define NQ     10
#define EPSF   1e-12f
#define L2E    1.4426950408889634f
#define MAXPTS 2048

__device__ float2       g_partials[NBLK];
__device__ unsigned int g_sem = 0;   // self-resetting via atomicInc wrap

__device__ __forceinline__ float fsqrt_approx(float s) {
    float d; asm("sqrt.approx.f32 %0, %1;" : "=f"(d) : "f"(s)); return d;
}
__device__ __forceinline__ float fex2_approx(float a) {
    float e; asm("ex2.approx.f32 %0, %1;" : "=f"(e) : "f"(a)); return e;
}

// invert linear tril index k -> (i, j), i > j
__device__ __forceinline__ void tril_invert(int k, int& i, int& j) {
    float r = fsqrt_approx(fmaf(8.0f, (float)k, 1.0f));
    i = (int)(0.5f * (1.0f + r));
    int tri = (i * (i - 1)) >> 1;
    if (k < tri)           { i--; tri -= i; }
    else if (k >= tri + i) { tri += i; i++; }
    j = k - tri;
}

// ---- shared epilogue: block reduce + last-block global reduce ----
__device__ __forceinline__ void block_and_grid_reduce(
    float acc_d, float acc_e, float beta, float t0, float tn,
    int n_events, float* __restrict__ out)
{
    #pragma unroll
    for (int o = 16; o > 0; o >>= 1) {
        acc_d += __shfl_down_sync(0xffffffffu, acc_d, o);
        acc_e += __shfl_down_sync(0xffffffffu, acc_e, o);
    }
    __shared__ float2 wred[TPB / 32];
    if ((threadIdx.x & 31) == 0)
        wred[threadIdx.x >> 5] = make_float2(acc_d, acc_e);
    __syncthreads();

    __shared__ bool is_last;
    if (threadIdx.x == 0) {
        float sd = 0.0f, se = 0.0f;
        #pragma unroll
        for (int w = 0; w < TPB / 32; w++) { sd += wred[w].x; se += wred[w].y; }
        g_partials[blockIdx.x] = make_float2(sd, se);
        __threadfence();
        unsigned old = atomicInc(&g_sem, gridDim.x - 1);
        is_last = (old == gridDim.x - 1);
    }
    __syncthreads();

    if (is_last) {
        double sd = 0.0, se = 0.0;
        const volatile float2* gp = (const volatile float2*)g_partials;
        for (int i = threadIdx.x; i < (int)gridDim.x; i += TPB) {
            sd += (double)gp[i].x;
            se += (double)gp[i].y;
        }
        #pragma unroll
        for (int o = 16; o > 0; o >>= 1) {
            sd += __shfl_down_sync(0xffffffffu, sd, o);
            se += __shfl_down_sync(0xffffffffu, se, o);
        }
        __shared__ double2 dred[TPB / 32];
        if ((threadIdx.x & 31) == 0)
            dred[threadIdx.x >> 5] = make_double2(sd, se);
        __syncthreads();
        if (threadIdx.x == 0) {
            double tsd = 0.0, tse = 0.0;
            #pragma unroll
            for (int w = 0; w < TPB / 32; w++) { tsd += dred[w].x; tse += dred[w].y; }
            double dtqD = ((double)tn - (double)t0) / (double)NQ;
            out[0] = (float)((double)beta * (double)n_events - tsd - dtqD * tse);
        }
    }
}

// ---- event term (2 events / iter) ----
__device__ __forceinline__ float event_sum(
    const float4* __restrict__ sm,
    const int2* __restrict__ data_uv, const float* __restrict__ data_t,
    int n_events, int tid, int stride)
{
    float acc_d = 0.0f;
    const int4*   uv4 = (const int4*)data_uv;
    const float2* tt2 = (const float2*)data_t;
    const int nev2 = n_events >> 1;
    for (int i = tid; i < nev2; i += stride) {
        int4   q  = uv4[i];
        float2 tt = tt2[i];
        float4 a0 = sm[q.x], b0 = sm[q.y];
        float4 a1 = sm[q.z], b1 = sm[q.w];
        float dx0 = fmaf(a0.z - b0.z, tt.x, a0.x - b0.x);
        float dy0 = fmaf(a0.w - b0.w, tt.x, a0.y - b0.y);
        float dx1 = fmaf(a1.z - b1.z, tt.y, a1.x - b1.x);
        float dy1 = fmaf(a1.w - b1.w, tt.y, a1.y - b1.y);
        acc_d += fsqrt_approx(fmaf(dx0, dx0, fmaf(dy0, dy0, EPSF)));
        acc_d += fsqrt_approx(fmaf(dx1, dx1, fmaf(dy1, dy1, EPSF)));
    }
    if ((n_events & 1) && tid == 0) {
        int   i = n_events - 1;
        int2  uv = data_uv[i];
        float t  = data_t[i];
        float4 a = sm[uv.x], b = sm[uv.y];
        float dx = fmaf(a.z - b.z, t, a.x - b.x);
        float dy = fmaf(a.w - b.w, t, a.y - b.y);
        acc_d += fsqrt_approx(fmaf(dx, dx, fmaf(dy, dy, EPSF)));
    }
    return acc_d;
}

// ====== struct kernel: computed pair indices (conflict-free LDS) + 2-pair ILP
__global__ __launch_bounds__(TPB, 4) void cvm_struct2_kernel(
    const float* __restrict__ z0, const float* __restrict__ v0,
    const float* __restrict__ beta_p, const float* __restrict__ data_t,
    const float* __restrict__ t0_p, const float* __restrict__ tn_p,
    const int2* __restrict__ data_uv,
    int n_points, int n_events, int n_pairs,
    float* __restrict__ out)
{
    __shared__ float4 sm[MAXPTS];
    {
        const float2* z2 = (const float2*)z0;
        const float2* v2 = (const float2*)v0;
        for (int i = threadIdx.x; i < n_points; i += TPB) {
            float2 z = z2[i];
            float2 v = v2[i];
            sm[i] = make_float4(z.x, z.y, v.x, v.y);
        }
    }
    __syncthreads();

    const float beta = *beta_p;
    const float t0   = *t0_p;
    const float tn   = *tn_p;
    const float dtq  = (tn - t0) * (1.0f / NQ);
    const float t05  = t0 + 0.5f * dtq;
    const float bL2E = beta * L2E;

    const int stride = NBLK * TPB;
    const int tid    = blockIdx.x * TPB + threadIdx.x;

    float acc_d = event_sum(sm, data_uv, data_t, n_events, tid, stride);

    // 2 pairs per thread via half-split: kA = idx, kB = idx + np2.
    // Both are consecutive within a warp -> sm[i] broadcast, sm[j] conflict-free.
    float eA0 = 0.0f, eA1 = 0.0f, eB0 = 0.0f, eB1 = 0.0f;
    const int np2 = n_pairs >> 1;
    for (int idx = tid; idx < np2; idx += stride) {
        int iA, jA, iB, jB;
        tril_invert(idx,        iA, jA);
        tril_invert(idx + np2,  iB, jB);

        float4 aA = sm[iA], bA = sm[jA];
        float4 aB = sm[iB], bB = sm[jB];

        float dxA = aA.x - bA.x, dyA = aA.y - bA.y;
        float vxA = aA.z - bA.z, vyA = aA.w - bA.w;
        float cA0 = fmaf(dxA, dxA, fmaf(dyA, dyA, EPSF));
        float cA1 = 2.0f * fmaf(dxA, vxA, dyA * vyA);
        float cA2 = fmaf(vxA, vxA, vyA * vyA);

        float dxB = aB.x - bB.x, dyB = aB.y - bB.y;
        float vxB = aB.z - bB.z, vyB = aB.w - bB.w;
        float cB0 = fmaf(dxB, dxB, fmaf(dyB, dyB, EPSF));
        float cB1 = 2.0f * fmaf(dxB, vxB, dyB * vyB);
        float cB2 = fmaf(vxB, vxB, vyB * vyB);

        #pragma unroll
        for (int q = 0; q < NQ; q++) {
            float t  = fmaf((float)q, dtq, t05);
            float sA = fmaf(fmaf(cA2, t, cA1), t, cA0);
            float sB = fmaf(fmaf(cB2, t, cB1), t, cB0);
            sA = fmaxf(sA, EPSF);             // cancellation guard (R4 NaN bug)
            sB = fmaxf(sB, EPSF);
            float dA = fsqrt_approx(sA);
            float dB = fsqrt_approx(sB);
            float eA = fex2_approx(fmaf(dA, -L2E, bL2E));
            float eB = fex2_approx(fmaf(dB, -L2E, bL2E));
            if (q & 1) { eA1 += eA; eB1 += eB; }
            else       { eA0 += eA; eB0 += eB; }
        }
    }
    // odd remainder pair
    if ((n_pairs & 1) && tid == 0) {
        int i, j;
        tril_invert(n_pairs - 1, i, j);
        float4 a = sm[i], b = sm[j];
        float dx = a.x - b.x, dy = a.y - b.y;
        float vx = a.z - b.z, vy = a.w - b.w;
        float c0 = fmaf(dx, dx, fmaf(dy, dy, EPSF));
        float c1 = 2.0f * fmaf(dx, vx, dy * vy);
        float c2 = fmaf(vx, vx, vy * vy);
        #pragma unroll
        for (int q = 0; q < NQ; q++) {
            float t = fmaf((float)q, dtq, t05);
            float s = fmaxf(fmaf(fmaf(c2, t, c1), t, c0), EPSF);
            eA0 += fex2_approx(fmaf(fsqrt_approx(s), -L2E, bL2E));
        }
    }

    block_and_grid_reduce(acc_d, (eA0 + eA1) + (eB0 + eB1),
                          beta, t0, tn, n_events, out);
}

// ============ fallback: gather kernel (R6 body) ============
__global__ __launch_bounds__(TPB, 4) void cvm_gather_kernel(
    const float* __restrict__ z0, const float* __restrict__ v0,
    const float* __restrict__ beta_p, const float* __restrict__ data_t,
    const float* __restrict__ t0_p, const float* __restrict__ tn_p,
    const int2* __restrict__ data_uv,
    const int* __restrict__ pair_u, const int* __restrict__ pair_v,
    int n_points, int n_events, int n_pairs,
    float* __restrict__ out)
{
    __shared__ float4 sm[MAXPTS];
    {
        const float2* z2 = (const float2*)z0;
        const float2* v2 = (const float2*)v0;
        for (int i = threadIdx.x; i < n_points; i += TPB) {
            float2 z = z2[i];
            float2 v = v2[i];
            sm[i] = make_float4(z.x, z.y, v.x, v.y);
        }
    }
    __syncthreads();

    const float beta = *beta_p;
    const float t0   = *t0_p;
    const float tn   = *tn_p;
    const float dtq  = (tn - t0) * (1.0f / NQ);
    const float t05  = t0 + 0.5f * dtq;
    const float bL2E = beta * L2E;

    const int stride = NBLK * TPB;
    const int tid    = blockIdx.x * TPB + threadIdx.x;

    float acc_d = event_sum(sm, data_uv, data_t, n_events, tid, stride);

    float e0 = 0.0f, e1 = 0.0f;
    for (int k = tid; k < n_pairs; k += stride) {
        float4 a = sm[pair_u[k]];
        float4 b = sm[pair_v[k]];
        float dx = a.x - b.x, dy = a.y - b.y;
        float vx = a.z - b.z, vy = a.w - b.w;
        float c0 = fmaf(dx, dx, fmaf(dy, dy, EPSF));
        float c1 = 2.0f * fmaf(dx, vx, dy * vy);
        float c2 = fmaf(vx, vx, vy * vy);
        #pragma unroll
        for (int q = 0; q < NQ; q++) {
            float t = fmaf((float)q, dtq, t05);
            float s = fmaxf(fmaf(fmaf(c2, t, c1), t, c0), EPSF);
            float d = fsqrt_approx(s);
            float e = fex2_approx(fmaf(d, -L2E, bL2E));
            if (q & 1) e1 += e; else e0 += e;
        }
    }

    block_and_grid_reduce(acc_d, e0 + e1, beta, t0, tn, n_events, out);
}

extern "C" void kernel_launch(void* const* d_in, const int* in_sizes, int n_in,
                              void* d_out, int out_size)
{
    // metadata order: z0, v0, beta, data_t, t0, tn, data_uv, pair_u, pair_v
    const float* z0      = (const float*)d_in[0];
    const float* v0      = (const float*)d_in[1];
    const float* beta_p  = (const float*)d_in[2];
    const float* data_t  = (const float*)d_in[3];
    const float* t0_p    = (const float*)d_in[4];
    const float* tn_p    = (const float*)d_in[5];
    const int2*  data_uv = (const int2*)d_in[6];
    const int*   pair_u  = (const int*)d_in[7];
    const int*   pair_v  = (const int*)d_in[8];
    float* out = (float*)d_out;

    int n_points = in_sizes[0] / 2;
    int n_events = in_sizes[3];
    int n_pairs  = in_sizes[7];

    long long full = (long long)n_points * (n_points - 1) / 2;
    if (n_points <= MAXPTS && full == (long long)n_pairs) {
        cvm_struct2_kernel<<<NBLK, TPB>>>(z0, v0, beta_p, data_t, t0_p, tn_p,
                                          data_uv, n_points, n_events, n_pairs, out);
    } else {
        cvm_gather_kernel<<<NBLK, TPB>>>(z0, v0, beta_p, data_t, t0_p, tn_p,
                                         data_uv, pair_u, pair_v,
                                         n_points, n_events, n_pairs, out);
    }
}

// round 9
// speedup vs baseline: 1.1889x; 1.1889x over previous
#include <cuda_runtime.h>
#include <cuda_bf16.h>

#define TPB    256
#define NBLK   592             // 148 SMs * 4 CTAs
#define EBLK   80              // event-role blocks (one per SM in wave 1)
#define NQ     10
#define EPSF   1e-12f
#define L2E    1.4426950408889634f
#define MAXPTS 2048

__device__ float2       g_partials[NBLK];
__device__ unsigned int g_sem = 0;   // self-resetting via atomicInc wrap

__device__ __forceinline__ float fsqrt_approx(float s) {
    float d; asm("sqrt.approx.f32 %0, %1;" : "=f"(d) : "f"(s)); return d;
}
__device__ __forceinline__ float fex2_approx(float a) {
    float e; asm("ex2.approx.f32 %0, %1;" : "=f"(e) : "f"(a)); return e;
}

// ---- shared epilogue: block reduce + last-block global reduce ----
__device__ __forceinline__ void block_and_grid_reduce(
    float acc_d, float acc_e, float beta, float t0, float tn,
    int n_events, float* __restrict__ out)
{
    #pragma unroll
    for (int o = 16; o > 0; o >>= 1) {
        acc_d += __shfl_down_sync(0xffffffffu, acc_d, o);
        acc_e += __shfl_down_sync(0xffffffffu, acc_e, o);
    }
    __shared__ float2 wred[TPB / 32];
    if ((threadIdx.x & 31) == 0)
        wred[threadIdx.x >> 5] = make_float2(acc_d, acc_e);
    __syncthreads();

    __shared__ bool is_last;
    if (threadIdx.x == 0) {
        float sd = 0.0f, se = 0.0f;
        #pragma unroll
        for (int w = 0; w < TPB / 32; w++) { sd += wred[w].x; se += wred[w].y; }
        g_partials[blockIdx.x] = make_float2(sd, se);
        __threadfence();
        unsigned old = atomicInc(&g_sem, gridDim.x - 1);
        is_last = (old == gridDim.x - 1);
    }
    __syncthreads();

    if (is_last) {
        double sd = 0.0, se = 0.0;
        const volatile float2* gp = (const volatile float2*)g_partials;
        for (int i = threadIdx.x; i < (int)gridDim.x; i += TPB) {
            sd += (double)gp[i].x;
            se += (double)gp[i].y;
        }
        #pragma unroll
        for (int o = 16; o > 0; o >>= 1) {
            sd += __shfl_down_sync(0xffffffffu, sd, o);
            se += __shfl_down_sync(0xffffffffu, se, o);
        }
        __shared__ double2 dred[TPB / 32];
        if ((threadIdx.x & 31) == 0)
            dred[threadIdx.x >> 5] = make_double2(sd, se);
        __syncthreads();
        if (threadIdx.x == 0) {
            double tsd = 0.0, tse = 0.0;
            #pragma unroll
            for (int w = 0; w < TPB / 32; w++) { tsd += dred[w].x; tse += dred[w].y; }
            double dtqD = ((double)tn - (double)t0) / (double)NQ;
            out[0] = (float)((double)beta * (double)n_events - tsd - dtqD * tse);
        }
    }
}

__global__ __launch_bounds__(TPB, 4) void cvm_split_kernel(
    const float* __restrict__ z0, const float* __restrict__ v0,
    const float* __restrict__ beta_p, const float* __restrict__ data_t,
    const float* __restrict__ t0_p, const float* __restrict__ tn_p,
    const int2* __restrict__ data_uv,
    const int* __restrict__ pair_u, const int* __restrict__ pair_v,
    int n_points, int n_events, int n_pairs,
    float* __restrict__ out)
{
    __shared__ float4 sm[MAXPTS];
    {
        const float2* z2 = (const float2*)z0;
        const float2* v2 = (const float2*)v0;
        for (int i = threadIdx.x; i < n_points; i += TPB) {
            float2 z = z2[i];
            float2 v = v2[i];
            sm[i] = make_float4(z.x, z.y, v.x, v.y);
        }
    }
    __syncthreads();

    const float beta = *beta_p;
    const float t0   = *t0_p;
    const float tn   = *tn_p;
    const float dtq  = (tn - t0) * (1.0f / NQ);
    const float t05  = t0 + 0.5f * dtq;
    const float bL2E = beta * L2E;

    float acc_d = 0.0f, acc_e = 0.0f;

    if (blockIdx.x < EBLK) {
        // ================= EVENT ROLE: 4 events / iter for MLP =================
        const int tid    = blockIdx.x * TPB + threadIdx.x;
        const int stride = EBLK * TPB;
        const int4*   uv4 = (const int4*)data_uv;
        const float4* tt4 = (const float4*)data_t;
        const int nev4 = n_events >> 2;
        for (int i = tid; i < nev4; i += stride) {
            int4   qa = uv4[2 * i];
            int4   qb = uv4[2 * i + 1];
            float4 tt = tt4[i];
            float4 a0 = sm[qa.x], b0 = sm[qa.y];
            float4 a1 = sm[qa.z], b1 = sm[qa.w];
            float4 a2 = sm[qb.x], b2 = sm[qb.y];
            float4 a3 = sm[qb.z], b3 = sm[qb.w];
            float dx0 = fmaf(a0.z - b0.z, tt.x, a0.x - b0.x);
            float dy0 = fmaf(a0.w - b0.w, tt.x, a0.y - b0.y);
            float dx1 = fmaf(a1.z - b1.z, tt.y, a1.x - b1.x);
            float dy1 = fmaf(a1.w - b1.w, tt.y, a1.y - b1.y);
            float dx2 = fmaf(a2.z - b2.z, tt.z, a2.x - b2.x);
            float dy2 = fmaf(a2.w - b2.w, tt.z, a2.y - b2.y);
            float dx3 = fmaf(a3.z - b3.z, tt.w, a3.x - b3.x);
            float dy3 = fmaf(a3.w - b3.w, tt.w, a3.y - b3.y);
            acc_d += fsqrt_approx(fmaf(dx0, dx0, fmaf(dy0, dy0, EPSF)));
            acc_d += fsqrt_approx(fmaf(dx1, dx1, fmaf(dy1, dy1, EPSF)));
            acc_d += fsqrt_approx(fmaf(dx2, dx2, fmaf(dy2, dy2, EPSF)));
            acc_d += fsqrt_approx(fmaf(dx3, dx3, fmaf(dy3, dy3, EPSF)));
        }
        // tail events [nev4*4, n_events) by first threads of block 0
        int tail0 = nev4 << 2;
        int ntail = n_events - tail0;
        if (blockIdx.x == 0 && threadIdx.x < ntail) {
            int   i  = tail0 + threadIdx.x;
            int2  uv = data_uv[i];
            float t  = data_t[i];
            float4 a = sm[uv.x], b = sm[uv.y];
            float dx = fmaf(a.z - b.z, t, a.x - b.x);
            float dy = fmaf(a.w - b.w, t, a.y - b.y);
            acc_d += fsqrt_approx(fmaf(dx, dx, fmaf(dy, dy, EPSF)));
        }
    } else {
        // ================ PAIR ROLE: 3 chains (3-way index split) ===============
        const int tid    = (blockIdx.x - EBLK) * TPB + threadIdx.x;
        const int stride = (NBLK - EBLK) * TPB;
        const int np3 = n_pairs / 3;

        float eA = 0.0f, eB = 0.0f, eC = 0.0f;
        for (int idx = tid; idx < np3; idx += stride) {
            int kA = idx, kB = idx + np3, kC = idx + 2 * np3;
            int uA = pair_u[kA], vA = pair_v[kA];
            int uB = pair_u[kB], vB = pair_v[kB];
            int uC = pair_u[kC], vC = pair_v[kC];
            float4 aA = sm[uA], bA = sm[vA];
            float4 aB = sm[uB], bB = sm[vB];
            float4 aC = sm[uC], bC = sm[vC];

            float dxA = aA.x - bA.x, dyA = aA.y - bA.y;
            float vxA = aA.z - bA.z, vyA = aA.w - bA.w;
            float cA0 = fmaf(dxA, dxA, fmaf(dyA, dyA, EPSF));
            float cA1 = 2.0f * fmaf(dxA, vxA, dyA * vyA);
            float cA2 = fmaf(vxA, vxA, vyA * vyA);

            float dxB = aB.x - bB.x, dyB = aB.y - bB.y;
            float vxB = aB.z - bB.z, vyB = aB.w - bB.w;
            float cB0 = fmaf(dxB, dxB, fmaf(dyB, dyB, EPSF));
            float cB1 = 2.0f * fmaf(dxB, vxB, dyB * vyB);
            float cB2 = fmaf(vxB, vxB, vyB * vyB);

            float dxC = aC.x - bC.x, dyC = aC.y - bC.y;
            float vxC = aC.z - bC.z, vyC = aC.w - bC.w;
            float cC0 = fmaf(dxC, dxC, fmaf(dyC, dyC, EPSF));
            float cC1 = 2.0f * fmaf(dxC, vxC, dyC * vyC);
            float cC2 = fmaf(vxC, vxC, vyC * vyC);

            float t = t05;
            #pragma unroll
            for (int q = 0; q < NQ; q++) {
                float sA = fmaxf(fmaf(fmaf(cA2, t, cA1), t, cA0), EPSF);
                float sB = fmaxf(fmaf(fmaf(cB2, t, cB1), t, cB0), EPSF);
                float sC = fmaxf(fmaf(fmaf(cC2, t, cC1), t, cC0), EPSF);
                float dA = fsqrt_approx(sA);
                float dB = fsqrt_approx(sB);
                float dC = fsqrt_approx(sC);
                eA += fex2_approx(fmaf(dA, -L2E, bL2E));
                eB += fex2_approx(fmaf(dB, -L2E, bL2E));
                eC += fex2_approx(fmaf(dC, -L2E, bL2E));
                t += dtq;
            }
        }
        // leftover pairs [3*np3, n_pairs): at most 2, first threads of block EBLK
        int left0 = 3 * np3;
        int nleft = n_pairs - left0;
        if (blockIdx.x == EBLK && threadIdx.x < nleft) {
            int k = left0 + threadIdx.x;
            float4 a = sm[pair_u[k]], b = sm[pair_v[k]];
            float dx = a.x - b.x, dy = a.y - b.y;
            float vx = a.z - b.z, vy = a.w - b.w;
            float c0 = fmaf(dx, dx, fmaf(dy, dy, EPSF));
            float c1 = 2.0f * fmaf(dx, vx, dy * vy);
            float c2 = fmaf(vx, vx, vy * vy);
            float t = t05;
            #pragma unroll
            for (int q = 0; q < NQ; q++) {
                float s = fmaxf(fmaf(fmaf(c2, t, c1), t, c0), EPSF);
                eA += fex2_approx(fmaf(fsqrt_approx(s), -L2E, bL2E));
                t += dtq;
            }
        }
        acc_e = (eA + eB) + eC;
    }

    block_and_grid_reduce(acc_d, acc_e, beta, t0, tn, n_events, out);
}

extern "C" void kernel_launch(void* const* d_in, const int* in_sizes, int n_in,
                              void* d_out, int out_size)
{
    // metadata order: z0, v0, beta, data_t, t0, tn, data_uv, pair_u, pair_v
    const float* z0      = (const float*)d_in[0];
    const float* v0      = (const float*)d_in[1];
    const float* beta_p  = (const float*)d_in[2];
    const float* data_t  = (const float*)d_in[3];
    const float* t0_p    = (const float*)d_in[4];
    const float* tn_p    = (const float*)d_in[5];
    const int2*  data_uv = (const int2*)d_in[6];
    const int*   pair_u  = (const int*)d_in[7];
    const int*   pair_v  = (const int*)d_in[8];
    float* out = (float*)d_out;

    int n_points = in_sizes[0] / 2;
    int n_events = in_sizes[3];
    int n_pairs  = in_sizes[7];

    cvm_split_kernel<<<NBLK, TPB>>>(z0, v0, beta_p, data_t, t0_p, tn_p,
                                    data_uv, pair_u, pair_v,
                                    n_points, n_events, n_pairs, out);
}